// round 9
// baseline (speedup 1.0000x reference)
#include <cuda_runtime.h>
#include <math.h>
#include <stdint.h>

// Problem constants
#define Bb   4
#define Ss   2048
#define Dd   1024

// Block tiling
#define BMT 128
#define BNT 128
#define BKT 32

// Padded strides (in uint2 elements) for conflict-free LDS.64 fragment reads
#define LDA2 36     // A/K tiles [rows][k]:  36 % 16 == 4  -> (4g+r)%16 2-to-1
#define LDB2 136    // B tiles  [k][cols]:  136 % 16 == 8  -> (8r+g)%16 2-to-1

// Scratch for Q, K, V (device globals: allocation-free rule)
static __device__ float g_Q[(size_t)Bb * Ss * Dd];
static __device__ float g_K[(size_t)Bb * Ss * Dd];
static __device__ float g_V[(size_t)Bb * Ss * Dd];

// ---------------------------------------------------------------------------
// tf32 helpers
// ---------------------------------------------------------------------------
__device__ __forceinline__ uint32_t f2tf(float v) {
    uint32_t r;
    asm("cvt.rna.tf32.f32 %0, %1;" : "=r"(r) : "f"(v));
    return r;
}

__device__ __forceinline__ uint2 split2(float v) {
    uint2 p;
    p.x = f2tf(v);
    p.y = f2tf(v - __uint_as_float(p.x));
    return p;
}

__device__ __forceinline__ void mma_tf32(float* d, const uint32_t* a, const uint32_t* b) {
    asm volatile(
        "mma.sync.aligned.m16n8k8.row.col.f32.tf32.tf32.f32 "
        "{%0,%1,%2,%3}, {%4,%5,%6,%7}, {%8,%9}, {%0,%1,%2,%3};"
        : "+f"(d[0]), "+f"(d[1]), "+f"(d[2]), "+f"(d[3])
        : "r"(a[0]), "r"(a[1]), "r"(a[2]), "r"(a[3]), "r"(b[0]), "r"(b[1]));
}

// 3-term product accumulate: hi*hi + hi*lo + lo*hi
__device__ __forceinline__ void mma3(float* acc, const uint2* a, const uint2* b) {
    uint32_t ahi[4] = {a[0].x, a[1].x, a[2].x, a[3].x};
    uint32_t alo[4] = {a[0].y, a[1].y, a[2].y, a[3].y};
    uint32_t bhi[2] = {b[0].x, b[1].x};
    uint32_t blo[2] = {b[0].y, b[1].y};
    mma_tf32(acc, ahi, bhi);
    mma_tf32(acc, ahi, blo);
    mma_tf32(acc, alo, bhi);
}

// ---------------------------------------------------------------------------
// Kernel 1: QKV projection.  out[8192,1024] = x[8192,1024] @ W[1024,1024]
// blockIdx.z selects weight/output. Pre-split hi/lo tiles in dynamic smem.
// ---------------------------------------------------------------------------
__global__ __launch_bounds__(256, 2) void qkv_tf32_kernel(
    const float* __restrict__ x,
    const float* __restrict__ Wq,
    const float* __restrict__ Wk,
    const float* __restrict__ Wv)
{
    extern __shared__ uint2 sh[];
    uint2* As2 = sh;                       // [BMT][LDA2]
    uint2* Bs2 = sh + BMT * LDA2;          // [BKT][LDB2]

    const float* W   = (blockIdx.z == 0) ? Wq : (blockIdx.z == 1) ? Wk : Wv;
    float*       out = (blockIdx.z == 0) ? g_Q : (blockIdx.z == 1) ? g_K : g_V;

    const int rowBase = blockIdx.y * BMT;
    const int colBase = blockIdx.x * BNT;
    const int tid  = threadIdx.x;
    const int warp = tid >> 5, lane = tid & 31;
    const int wm = warp & 1, wn = warp >> 1;
    const int g = lane >> 2, r = lane & 3;

    float acc[4][4][4] = {};

    for (int k0 = 0; k0 < Dd; k0 += BKT) {
        // A tile: 128x32 floats -> split uint2
        #pragma unroll
        for (int i = 0; i < 4; i++) {
            int idx = tid + i * 256;
            int row = idx >> 3, c4 = (idx & 7) * 4;
            float4 v = *(const float4*)&x[(size_t)(rowBase + row) * Dd + k0 + c4];
            uint2* p = &As2[row * LDA2 + c4];
            p[0] = split2(v.x); p[1] = split2(v.y); p[2] = split2(v.z); p[3] = split2(v.w);
        }
        // B tile: 32x128 floats -> split uint2
        #pragma unroll
        for (int i = 0; i < 4; i++) {
            int idx = tid + i * 256;
            int row = idx >> 5, c4 = (idx & 31) * 4;
            float4 v = *(const float4*)&W[(size_t)(k0 + row) * Dd + colBase + c4];
            uint2* p = &Bs2[row * LDB2 + c4];
            p[0] = split2(v.x); p[1] = split2(v.y); p[2] = split2(v.z); p[3] = split2(v.w);
        }
        __syncthreads();

        #pragma unroll
        for (int ks = 0; ks < 4; ks++) {
            const int kk = ks * 8;
            uint2 af[4][4];
            #pragma unroll
            for (int t = 0; t < 4; t++) {
                int row0 = wm * 64 + t * 16 + g;
                af[t][0] = As2[ row0      * LDA2 + kk + r    ];
                af[t][1] = As2[(row0 + 8) * LDA2 + kk + r    ];
                af[t][2] = As2[ row0      * LDA2 + kk + r + 4];
                af[t][3] = As2[(row0 + 8) * LDA2 + kk + r + 4];
            }
            uint2 bf[4][2];
            #pragma unroll
            for (int u = 0; u < 4; u++) {
                int n = wn * 32 + u * 8 + g;
                bf[u][0] = Bs2[(kk + r    ) * LDB2 + n];
                bf[u][1] = Bs2[(kk + r + 4) * LDB2 + n];
            }
            #pragma unroll
            for (int t = 0; t < 4; t++)
                #pragma unroll
                for (int u = 0; u < 4; u++)
                    mma3(acc[t][u], af[t], bf[u]);
        }
        __syncthreads();
    }

    #pragma unroll
    for (int t = 0; t < 4; t++)
        #pragma unroll
        for (int u = 0; u < 4; u++) {
            int row0 = rowBase + wm * 64 + t * 16 + g;
            int col  = colBase + wn * 32 + u * 8 + 2 * r;
            *(float2*)&out[(size_t)row0 * Dd + col]       = make_float2(acc[t][u][0], acc[t][u][1]);
            *(float2*)&out[(size_t)(row0 + 8) * Dd + col] = make_float2(acc[t][u][2], acc[t][u][3]);
        }
}

// ---------------------------------------------------------------------------
// Kernel 2: raw scores = Q @ K^T per batch, causal tile skip.
// K kept row-major [n][k]; B fragment read as Ks2[n][k].
// ---------------------------------------------------------------------------
__global__ __launch_bounds__(256, 2) void scores_tf32_kernel(float* __restrict__ wts)
{
    const int b = blockIdx.z;
    const int rowBase = blockIdx.y * BMT;
    const int colBase = blockIdx.x * BNT;
    if (colBase > rowBase + BMT - 1) return;

    const float* Q  = g_Q + (size_t)b * Ss * Dd;
    const float* Kp = g_K + (size_t)b * Ss * Dd;
    float* C = wts + (size_t)b * Ss * Ss;

    extern __shared__ uint2 sh[];
    uint2* As2 = sh;                     // [BMT][LDA2]
    uint2* Ks2 = sh + BMT * LDA2;        // [BNT][LDA2]

    const int tid  = threadIdx.x;
    const int warp = tid >> 5, lane = tid & 31;
    const int wm = warp & 1, wn = warp >> 1;
    const int g = lane >> 2, r = lane & 3;

    float acc[4][4][4] = {};

    for (int k0 = 0; k0 < Dd; k0 += BKT) {
        #pragma unroll
        for (int i = 0; i < 4; i++) {
            int idx = tid + i * 256;
            int row = idx >> 3, c4 = (idx & 7) * 4;
            float4 v = *(const float4*)&Q[(size_t)(rowBase + row) * Dd + k0 + c4];
            uint2* p = &As2[row * LDA2 + c4];
            p[0] = split2(v.x); p[1] = split2(v.y); p[2] = split2(v.z); p[3] = split2(v.w);
            float4 w = *(const float4*)&Kp[(size_t)(colBase + row) * Dd + k0 + c4];
            uint2* q = &Ks2[row * LDA2 + c4];
            q[0] = split2(w.x); q[1] = split2(w.y); q[2] = split2(w.z); q[3] = split2(w.w);
        }
        __syncthreads();

        #pragma unroll
        for (int ks = 0; ks < 4; ks++) {
            const int kk = ks * 8;
            uint2 af[4][4];
            #pragma unroll
            for (int t = 0; t < 4; t++) {
                int row0 = wm * 64 + t * 16 + g;
                af[t][0] = As2[ row0      * LDA2 + kk + r    ];
                af[t][1] = As2[(row0 + 8) * LDA2 + kk + r    ];
                af[t][2] = As2[ row0      * LDA2 + kk + r + 4];
                af[t][3] = As2[(row0 + 8) * LDA2 + kk + r + 4];
            }
            uint2 bf[4][2];
            #pragma unroll
            for (int u = 0; u < 4; u++) {
                int n = wn * 32 + u * 8 + g;
                bf[u][0] = Ks2[n * LDA2 + kk + r    ];
                bf[u][1] = Ks2[n * LDA2 + kk + r + 4];
            }
            #pragma unroll
            for (int t = 0; t < 4; t++)
                #pragma unroll
                for (int u = 0; u < 4; u++)
                    mma3(acc[t][u], af[t], bf[u]);
        }
        __syncthreads();
    }

    #pragma unroll
    for (int t = 0; t < 4; t++)
        #pragma unroll
        for (int u = 0; u < 4; u++) {
            int row0 = rowBase + wm * 64 + t * 16 + g;
            int col  = colBase + wn * 32 + u * 8 + 2 * r;
            *(float2*)&C[(size_t)row0 * Ss + col]       = make_float2(acc[t][u][0], acc[t][u][1]);
            *(float2*)&C[(size_t)(row0 + 8) * Ss + col] = make_float2(acc[t][u][2], acc[t][u][3]);
        }
}

// ---------------------------------------------------------------------------
// Kernel 3: causal softmax in-place.
// ---------------------------------------------------------------------------
__global__ __launch_bounds__(256) void softmax_kernel(float* __restrict__ wts)
{
    const int b = blockIdx.y;
    const int i = blockIdx.x;
    float* row = wts + ((size_t)b * Ss + i) * Ss;
    const int n = i + 1;
    const float scale = 0.03125f;   // 1/sqrt(1024)

    __shared__ float srow[Ss];
    __shared__ float red[8];
    const int tid = threadIdx.x;
    const int lane = tid & 31, warp = tid >> 5;

    float mx = -INFINITY;
    for (int j = tid; j < n; j += 256) {
        float v = row[j] * scale;
        srow[j] = v;
        mx = fmaxf(mx, v);
    }
    #pragma unroll
    for (int o = 16; o; o >>= 1) mx = fmaxf(mx, __shfl_xor_sync(~0u, mx, o));
    if (lane == 0) red[warp] = mx;
    __syncthreads();
    float bmax = -INFINITY;
    #pragma unroll
    for (int w = 0; w < 8; w++) bmax = fmaxf(bmax, red[w]);
    __syncthreads();

    float sum = 0.0f;
    for (int j = tid; j < n; j += 256) {
        float e = __expf(srow[j] - bmax);
        srow[j] = e;
        sum += e;
    }
    #pragma unroll
    for (int o = 16; o; o >>= 1) sum += __shfl_xor_sync(~0u, sum, o);
    if (lane == 0) red[warp] = sum;
    __syncthreads();
    float bsum = 0.0f;
    #pragma unroll
    for (int w = 0; w < 8; w++) bsum += red[w];
    const float inv = 1.0f / bsum;

    for (int j = tid; j < Ss; j += 256)
        row[j] = (j < n) ? srow[j] * inv : 0.0f;
}

// ---------------------------------------------------------------------------
// Kernel 4: att_output = weights @ V per batch, causal K truncation.
// ---------------------------------------------------------------------------
__global__ __launch_bounds__(256, 2) void av_tf32_kernel(
    const float* __restrict__ wts, float* __restrict__ out)
{
    const int b = blockIdx.z;
    const int rowBase = blockIdx.y * BMT;
    const int colBase = blockIdx.x * BNT;

    const float* Wm = wts + (size_t)b * Ss * Ss;
    const float* V  = g_V + (size_t)b * Ss * Dd;
    float* C = out + (size_t)b * Ss * Dd;

    extern __shared__ uint2 sh[];
    uint2* As2 = sh;                       // [BMT][LDA2]
    uint2* Bs2 = sh + BMT * LDA2;          // [BKT][LDB2]

    const int tid  = threadIdx.x;
    const int warp = tid >> 5, lane = tid & 31;
    const int wm = warp & 1, wn = warp >> 1;
    const int g = lane >> 2, r = lane & 3;

    float acc[4][4][4] = {};
    const int kMax = rowBase + BMT;

    for (int k0 = 0; k0 < kMax; k0 += BKT) {
        #pragma unroll
        for (int i = 0; i < 4; i++) {
            int idx = tid + i * 256;
            int row = idx >> 3, c4 = (idx & 7) * 4;
            float4 v = *(const float4*)&Wm[(size_t)(rowBase + row) * Ss + k0 + c4];
            uint2* p = &As2[row * LDA2 + c4];
            p[0] = split2(v.x); p[1] = split2(v.y); p[2] = split2(v.z); p[3] = split2(v.w);
        }
        #pragma unroll
        for (int i = 0; i < 4; i++) {
            int idx = tid + i * 256;
            int row = idx >> 5, c4 = (idx & 31) * 4;
            float4 v = *(const float4*)&V[(size_t)(k0 + row) * Dd + colBase + c4];
            uint2* p = &Bs2[row * LDB2 + c4];
            p[0] = split2(v.x); p[1] = split2(v.y); p[2] = split2(v.z); p[3] = split2(v.w);
        }
        __syncthreads();

        #pragma unroll
        for (int ks = 0; ks < 4; ks++) {
            const int kk = ks * 8;
            uint2 af[4][4];
            #pragma unroll
            for (int t = 0; t < 4; t++) {
                int row0 = wm * 64 + t * 16 + g;
                af[t][0] = As2[ row0      * LDA2 + kk + r    ];
                af[t][1] = As2[(row0 + 8) * LDA2 + kk + r    ];
                af[t][2] = As2[ row0      * LDA2 + kk + r + 4];
                af[t][3] = As2[(row0 + 8) * LDA2 + kk + r + 4];
            }
            uint2 bf[4][2];
            #pragma unroll
            for (int u = 0; u < 4; u++) {
                int n = wn * 32 + u * 8 + g;
                bf[u][0] = Bs2[(kk + r    ) * LDB2 + n];
                bf[u][1] = Bs2[(kk + r + 4) * LDB2 + n];
            }
            #pragma unroll
            for (int t = 0; t < 4; t++)
                #pragma unroll
                for (int u = 0; u < 4; u++)
                    mma3(acc[t][u], af[t], bf[u]);
        }
        __syncthreads();
    }

    #pragma unroll
    for (int t = 0; t < 4; t++)
        #pragma unroll
        for (int u = 0; u < 4; u++) {
            int row0 = rowBase + wm * 64 + t * 16 + g;
            int col  = colBase + wn * 32 + u * 8 + 2 * r;
            *(float2*)&C[(size_t)row0 * Dd + col]       = make_float2(acc[t][u][0], acc[t][u][1]);
            *(float2*)&C[(size_t)(row0 + 8) * Dd + col] = make_float2(acc[t][u][2], acc[t][u][3]);
        }
}

// ---------------------------------------------------------------------------
extern "C" void kernel_launch(void* const* d_in, const int* in_sizes, int n_in,
                              void* d_out, int out_size)
{
    const float* x  = (const float*)d_in[0];
    const float* Wq = (const float*)d_in[1];
    const float* Wk = (const float*)d_in[2];
    const float* Wv = (const float*)d_in[3];

    float* out = (float*)d_out;                  // att_output [4,2048,1024]
    float* wts = out + (size_t)Bb * Ss * Dd;     // att_weights [4,2048,2048]

    const int smemAB = (BMT * LDA2 + BKT * LDB2) * (int)sizeof(uint2);  // 71680
    const int smemQK = (BMT * LDA2 + BNT * LDA2) * (int)sizeof(uint2);  // 73728

    static bool attr_done = false;
    if (!attr_done) {
        cudaFuncSetAttribute(qkv_tf32_kernel,    cudaFuncAttributeMaxDynamicSharedMemorySize, smemAB);
        cudaFuncSetAttribute(scores_tf32_kernel, cudaFuncAttributeMaxDynamicSharedMemorySize, smemQK);
        cudaFuncSetAttribute(av_tf32_kernel,     cudaFuncAttributeMaxDynamicSharedMemorySize, smemAB);
        attr_done = true;
    }

    qkv_tf32_kernel<<<dim3(Dd / BNT, (Bb * Ss) / BMT, 3), 256, smemAB>>>(x, Wq, Wk, Wv);
    scores_tf32_kernel<<<dim3(Ss / BNT, Ss / BMT, Bb), 256, smemQK>>>(wts);
    softmax_kernel<<<dim3(Ss, Bb), 256>>>(wts);
    av_tf32_kernel<<<dim3(Dd / BNT, Ss / BMT, Bb), 256, smemAB>>>(wts, out);
}